// round 16
// baseline (speedup 1.0000x reference)
#include <cuda_runtime.h>
#include <cuda_fp16.h>
#include <math.h>

#define N_TOK 9216
#define DIMC  128

// ---------------- scratch ----------------
__device__ __half g_q [2u * N_TOK * DIMC];     // [br][n][d] fp16, 0.25*log2e*mask folded
__device__ __half g_k [2u * N_TOK * DIMC];     // [br][n][d] fp16, mask folded
__device__ __half g_v [2u * N_TOK * DIMC];     // [br][d][n] fp16 (transposed), mask folded
__device__ __half g_on[2u * N_TOK * DIMC];     // [br][n][d] fp16 attention output
__device__ __half g_amh[(size_t)N_TOK * DIMC]; // [pixel][ch] fp16 (proj out)
__device__ __half g_wh [9u * DIMC * DIMC];     // [tap][oc][ic] fp16 conv weights
__device__ __half g_wqkv[6u * DIMC * DIMC];    // [b][d][c] fp16 qkv weights
__device__ __half g_pwh[2u * DIMC * DIMC];     // [br][e][d] fp16 proj weights

extern __shared__ char dynsm[];

// ---------------- helpers ----------------
__device__ __forceinline__ unsigned smem_u32(const void* p) {
    unsigned a;
    asm("{ .reg .u64 t; cvta.to.shared.u64 t, %1; cvt.u32.u64 %0, t; }" : "=r"(a) : "l"(p));
    return a;
}
__device__ __forceinline__ void cp16(unsigned dst, const void* src) {
    asm volatile("cp.async.cg.shared.global [%0], [%1], 16;" :: "r"(dst), "l"(src));
}
#define CP_COMMIT() asm volatile("cp.async.commit_group;" ::: "memory")
#define CP_WAIT(n)  asm volatile("cp.async.wait_group %0;" :: "n"(n) : "memory")

__device__ __forceinline__ void mma16(float* d, unsigned a0, unsigned a1, unsigned a2,
                                      unsigned a3, unsigned b0, unsigned b1) {
    asm volatile("mma.sync.aligned.m16n8k16.row.col.f32.f16.f16.f32 "
        "{%0,%1,%2,%3}, {%4,%5,%6,%7}, {%8,%9}, {%0,%1,%2,%3};"
        : "+f"(d[0]), "+f"(d[1]), "+f"(d[2]), "+f"(d[3])
        : "r"(a0), "r"(a1), "r"(a2), "r"(a3), "r"(b0), "r"(b1));
}
__device__ __forceinline__ void ldsm4(unsigned& r0, unsigned& r1, unsigned& r2,
                                      unsigned& r3, unsigned addr) {
    asm volatile("ldmatrix.sync.aligned.m8n8.x4.shared.b16 {%0,%1,%2,%3}, [%4];"
        : "=r"(r0), "=r"(r1), "=r"(r2), "=r"(r3) : "r"(addr));
}
__device__ __forceinline__ unsigned packh2(float lo, float hi) {
    __half2 h = __floats2half2_rn(lo, hi);
    return *(unsigned*)&h;
}
__device__ __forceinline__ float ex2(float x) {
    float r;
    asm("ex2.approx.f32 %0, %1;" : "=f"(r) : "f"(x));
    return r;
}

// ---------------------------------------------------------------------------
// Kernel 0: fp16 weight prep.
// ---------------------------------------------------------------------------
__global__ void prep_w_kernel(const float* __restrict__ cw,
                              const float* __restrict__ qwo, const float* __restrict__ kwo,
                              const float* __restrict__ vwo,
                              const float* __restrict__ qwb, const float* __restrict__ kwb,
                              const float* __restrict__ vwb,
                              const float* __restrict__ pwo, const float* __restrict__ pwb)
{
    int i = blockIdx.x * 256 + threadIdx.x;
    if (i < 9 * 128 * 128) {
        int tap = i >> 14;
        int rem = i & 16383;
        int oc  = rem >> 7;
        int ic  = rem & 127;
        g_wh[i] = __float2half(cw[((size_t)oc * 128 + ic) * 9 + tap]);
    }
    if (i < 6 * 16384) {
        int b = i >> 14, e = i & 16383;
        const float* W = (b == 0) ? qwo : (b == 1) ? kwo : (b == 2) ? vwo
                       : (b == 3) ? qwb : (b == 4) ? kwb : vwb;
        g_wqkv[i] = __float2half(W[e]);
    }
    if (i < 2 * 16384) {
        int b = i >> 14, e = i & 16383;
        g_pwh[i] = __float2half(b ? pwb[e] : pwo[e]);
    }
}

// ---------------------------------------------------------------------------
// Kernel 1: qkv via mma.  grid (72, 3) — kind-major, both branches per CTA.
// ---------------------------------------------------------------------------
#define PAD  136
#define PADW 68
#define TILEB 34816u     // 128*136*2 bytes

__global__ void __launch_bounds__(256) qkv_mma_kernel(const float* __restrict__ x,
                                                      const float* __restrict__ fm,
                                                      const float* __restrict__ hm)
{
    __half* smh = (__half*)dynsm;           // A [128][136] | W0 | W1
    unsigned sb = smem_u32(dynsm);

    int kind = blockIdx.y;
    int nb   = blockIdx.x * 128;
    int tid = threadIdx.x;
    int warp = tid >> 5, lane = tid & 31;
    int rg = lane >> 2, cg = lane & 3;
    int q0 = warp * 16;
    const float* X = (kind == 1) ? fm : x;

    #pragma unroll
    for (int br = 0; br < 2; br++) {
        const __half* Wg = g_wqkv + (size_t)(br * 3 + kind) * DIMC * DIMC;
        unsigned wd = sb + (unsigned)(1 + br) * TILEB;
        #pragma unroll
        for (int t = 0; t < 8; t++) {
            int i = t * 256 + tid;
            int d = i >> 4, seg = i & 15;
            cp16(wd + (unsigned)d * (PAD * 2) + (unsigned)seg * 16u,
                 (const char*)(Wg + (size_t)d * DIMC) + seg * 16);
        }
    }
    CP_COMMIT();

    unsigned* At2 = (unsigned*)smh;
    #pragma unroll
    for (int t = 0; t < 32; t++) {
        int idx = t * 256 + tid;
        int n = idx & 127, cp = idx >> 7;
        float v0 = X[(size_t)(2 * cp)     * N_TOK + nb + n];
        float v1 = X[(size_t)(2 * cp + 1) * N_TOK + nb + n];
        At2[n * PADW + cp] = packh2(v0, v1);
    }
    CP_WAIT(0);
    __syncthreads();

    unsigned af[8][4];
    #pragma unroll
    for (int k = 0; k < 8; k++) {
        int k0 = k * 16;
        af[k][0] = *(const unsigned*)(smh + (q0 + rg)     * PAD + k0 + 2 * cg);
        af[k][1] = *(const unsigned*)(smh + (q0 + rg + 8) * PAD + k0 + 2 * cg);
        af[k][2] = *(const unsigned*)(smh + (q0 + rg)     * PAD + k0 + 8 + 2 * cg);
        af[k][3] = *(const unsigned*)(smh + (q0 + rg + 8) * PAD + k0 + 8 + 2 * cg);
    }

    float qs = (kind == 0) ? 0.25f * 1.44269504f : 1.0f;
    int tok0 = nb + q0 + rg, tok1 = tok0 + 8;
    float h0 = hm[tok0], h1 = hm[tok1];

    #pragma unroll
    for (int br = 0; br < 2; br++) {
        const __half* Wsm = smh + (1 + br) * (128 * PAD);
        float acc[16][4];
        #pragma unroll
        for (int n = 0; n < 16; n++)
            #pragma unroll
            for (int r = 0; r < 4; r++) acc[n][r] = 0.f;

        #pragma unroll
        for (int k = 0; k < 8; k++) {
            int k0 = k * 16;
            #pragma unroll
            for (int n = 0; n < 16; n++) {
                unsigned b0 = *(const unsigned*)(Wsm + (n * 8 + rg) * PAD + k0 + 2 * cg);
                unsigned b1 = *(const unsigned*)(Wsm + (n * 8 + rg) * PAD + k0 + 8 + 2 * cg);
                mma16(acc[n], af[k][0], af[k][1], af[k][2], af[k][3], b0, b1);
            }
        }

        float f0 = ((br == 0) ? (h0 > 0.3f ? 1.f : 0.01f) : (h0 > 0.3f ? 0.01f : 1.f)) * qs;
        float f1 = ((br == 0) ? (h1 > 0.3f ? 1.f : 0.01f) : (h1 > 0.3f ? 0.01f : 1.f)) * qs;

        if (kind != 2) {
            __half* out = ((kind == 0) ? g_q : g_k) + (size_t)br * N_TOK * DIMC;
            #pragma unroll
            for (int n = 0; n < 16; n++) {
                int col = n * 8 + 2 * cg;
                *(unsigned*)(out + (size_t)tok0 * DIMC + col) = packh2(acc[n][0] * f0, acc[n][1] * f0);
                *(unsigned*)(out + (size_t)tok1 * DIMC + col) = packh2(acc[n][2] * f1, acc[n][3] * f1);
            }
        } else {
            __half* tb = smh + 1 * (128 * PAD);
            __syncthreads();
            #pragma unroll
            for (int n = 0; n < 16; n++) {
                int col = n * 8 + 2 * cg;
                tb[(col)     * PAD + q0 + rg]     = __float2half(acc[n][0] * f0);
                tb[(col + 1) * PAD + q0 + rg]     = __float2half(acc[n][1] * f0);
                tb[(col)     * PAD + q0 + rg + 8] = __float2half(acc[n][2] * f1);
                tb[(col + 1) * PAD + q0 + rg + 8] = __float2half(acc[n][3] * f1);
            }
            __syncthreads();
            __half* outv = g_v + (size_t)br * N_TOK * DIMC;
            #pragma unroll
            for (int t = 0; t < 8; t++) {
                int i = t * 256 + tid;
                int d = i >> 4, seg = i & 15;
                uint4 v = *(const uint4*)(tb + d * PAD + seg * 8);
                *(uint4*)((char*)(outv + (size_t)d * N_TOK + nb) + seg * 16) = v;
            }
        }
    }
}

// ---------------------------------------------------------------------------
// Kernel 2: fp16 flash attention (R8 compute structure; depth-2 prefetch:
// tile j gets two full compute iterations to land).  grid (72, 2), 256 thr.
// ---------------------------------------------------------------------------
#define QSTRH  136
#define QROWB  272u
#define KV_OFF 34816u
#define KBYTES 17408u
#define BUF_SZ 35840u
#define SMEM_FLASH 142336u      // Q + 3 KV buffers

__device__ __forceinline__ void load_kv_async(const __half* __restrict__ Kg,
                                              const __half* __restrict__ Vg,
                                              unsigned sb, int kb, unsigned bufoff, int tid)
{
    #pragma unroll
    for (int t = 0; t < 4; t++) {
        int c = t * 256 + tid;
        int row = c >> 4, i = c & 15;
        cp16(sb + bufoff + (unsigned)row * QROWB + (unsigned)i * 16u,
             (const char*)(Kg + (size_t)(kb + row) * DIMC) + i * 16);
    }
    #pragma unroll
    for (int t = 0; t < 4; t++) {
        int c = t * 256 + tid;
        int row = c >> 3, i = c & 7;
        cp16(sb + bufoff + KBYTES + (unsigned)row * 144u + (unsigned)i * 16u,
             (const char*)(Vg + (size_t)row * N_TOK + kb) + i * 16);
    }
}

__global__ void __launch_bounds__(256, 1) flash_mma_kernel()
{
    const __half* smh = (const __half*)dynsm;
    unsigned sb = smem_u32(dynsm);
    int tid  = threadIdx.x;
    int warp = tid >> 5, lane = tid & 31;
    int branch = blockIdx.y;
    int qb     = blockIdx.x * 128;

    const __half* Qg = g_q + (size_t)branch * N_TOK * DIMC;
    const __half* Kg = g_k + (size_t)branch * N_TOK * DIMC;
    const __half* Vg = g_v + (size_t)branch * N_TOK * DIMC;

    // prologue: Q (group 0), kv tile 0 (group 1), kv tile 1 (group 2)
    #pragma unroll
    for (int t = 0; t < 8; t++) {
        int c = t * 256 + tid;
        int row = c >> 4, i = c & 15;
        cp16(sb + (unsigned)row * QROWB + (unsigned)i * 16u,
             (const char*)(Qg + (size_t)(qb + row) * DIMC) + i * 16);
    }
    CP_COMMIT();
    load_kv_async(Kg, Vg, sb, 0, KV_OFF + 0u * BUF_SZ, tid);
    CP_COMMIT();
    load_kv_async(Kg, Vg, sb, 64, KV_OFF + 1u * BUF_SZ, tid);
    CP_COMMIT();

    int q0 = warp * 16;
    int rg = lane >> 2;
    int cg = lane & 3;

    CP_WAIT(2);            // Q resident
    __syncthreads();

    unsigned qf[8][4];
    #pragma unroll
    for (int k = 0; k < 8; k++) {
        int k0 = k * 16;
        qf[k][0] = *(const unsigned*)(smh + (q0 + rg)     * QSTRH + k0 + 2 * cg);
        qf[k][1] = *(const unsigned*)(smh + (q0 + rg + 8) * QSTRH + k0 + 2 * cg);
        qf[k][2] = *(const unsigned*)(smh + (q0 + rg)     * QSTRH + k0 + 8 + 2 * cg);
        qf[k][3] = *(const unsigned*)(smh + (q0 + rg + 8) * QSTRH + k0 + 8 + 2 * cg);
    }

    unsigned rowsel = (unsigned)(((lane >> 4) * 8 + (lane & 7)));
    unsigned kh16   = (unsigned)(((lane >> 3) & 1) * 16);

    float o[16][4];
    #pragma unroll
    for (int n = 0; n < 16; n++)
        #pragma unroll
        for (int r = 0; r < 4; r++) o[n][r] = 0.f;
    float l0 = 0.f, l1 = 0.f;

    for (int j = 0; j < 144; j++) {
        // tile j was committed two iterations ago; at most one newer group
        // ({j+1}) is outstanding, so wait(1) guarantees tile j has landed.
        if (j + 1 < 144) CP_WAIT(1); else CP_WAIT(0);
        __syncthreads();    // all threads' tile-j data visible; iter j-1 reads done

        // issue load of tile j+2 into buffer (j+2)%3 == (j-1)%3 (safe post-barrier)
        if (j + 2 < 144) {
            load_kv_async(Kg, Vg, sb, (j + 2) * 64,
                          KV_OFF + (unsigned)((j + 2) % 3) * BUF_SZ, tid);
            CP_COMMIT();
        }

        unsigned KrowB = sb + KV_OFF + (unsigned)(j % 3) * BUF_SZ + rowsel * 272u + kh16;
        unsigned VrowB = sb + KV_OFF + (unsigned)(j % 3) * BUF_SZ + KBYTES + rowsel * 144u + kh16;

        // ---- S = Q . K^T ----
        float s[8][4];
        #pragma unroll
        for (int n = 0; n < 8; n++)
            #pragma unroll
            for (int r = 0; r < 4; r++) s[n][r] = 0.f;

        #pragma unroll
        for (int k = 0; k < 8; k++) {
            #pragma unroll
            for (int g = 0; g < 4; g++) {
                unsigned b0a, b1a, b0b, b1b;
                ldsm4(b0a, b1a, b0b, b1b, KrowB + (unsigned)g * 4352u + (unsigned)k * 32u);
                mma16(s[2 * g],     qf[k][0], qf[k][1], qf[k][2], qf[k][3], b0a, b1a);
                mma16(s[2 * g + 1], qf[k][0], qf[k][1], qf[k][2], qf[k][3], b0b, b1b);
            }
        }

        // ---- P = exp2(S) (log2e pre-folded); rowsum; pack ----
        unsigned ph0[8], ph1[8];
        #pragma unroll
        for (int n = 0; n < 8; n++) {
            float p0 = ex2(s[n][0]);
            float p1 = ex2(s[n][1]);
            float p2 = ex2(s[n][2]);
            float p3 = ex2(s[n][3]);
            l0 += p0 + p1;
            l1 += p2 + p3;
            ph0[n] = packh2(p0, p1);
            ph1[n] = packh2(p2, p3);
        }

        // ---- O += P . V ----
        #pragma unroll
        for (int kb2 = 0; kb2 < 4; kb2++) {
            unsigned a0 = ph0[2 * kb2];
            unsigned a1 = ph1[2 * kb2];
            unsigned a2 = ph0[2 * kb2 + 1];
            unsigned a3 = ph1[2 * kb2 + 1];
            #pragma unroll
            for (int g = 0; g < 8; g++) {
                unsigned b0a, b1a, b0b, b1b;
                ldsm4(b0a, b1a, b0b, b1b, VrowB + (unsigned)g * 2304u + (unsigned)kb2 * 32u);
                mma16(o[2 * g],     a0, a1, a2, a3, b0a, b1a);
                mma16(o[2 * g + 1], a0, a1, a2, a3, b0b, b1b);
            }
        }
    }

    l0 += __shfl_xor_sync(0xffffffffu, l0, 1);
    l0 += __shfl_xor_sync(0xffffffffu, l0, 2);
    l1 += __shfl_xor_sync(0xffffffffu, l1, 1);
    l1 += __shfl_xor_sync(0xffffffffu, l1, 2);
    float inv0 = 1.f / l0, inv1 = 1.f / l1;

    __half* On = g_on + (size_t)branch * N_TOK * DIMC;
    int row_lo = qb + q0 + rg;
    int row_hi = row_lo + 8;
    #pragma unroll
    for (int n = 0; n < 16; n++) {
        int col = n * 8 + 2 * cg;
        *(unsigned*)(On + (size_t)row_lo * DIMC + col) = packh2(o[n][0] * inv0, o[n][1] * inv0);
        *(unsigned*)(On + (size_t)row_hi * DIMC + col) = packh2(o[n][2] * inv1, o[n][3] * inv1);
    }
}

// ---------------------------------------------------------------------------
// Kernel 3: projection via mma.  grid 144 (64-token tiles), 256 threads.
// ---------------------------------------------------------------------------
#define PROJ_SMEM 104448u

__global__ void __launch_bounds__(256) proj_mma_kernel(const float* __restrict__ pbo,
                                                       const float* __restrict__ pbb)
{
    __half* smh = (__half*)dynsm;
    unsigned sb = smem_u32(dynsm);
    int nb  = blockIdx.x * 64;
    int tid = threadIdx.x;
    int warp = tid >> 5, lane = tid & 31;
    int rg = lane >> 2, cg = lane & 3;
    int q0 = (warp & 3) * 16;
    int e0 = (warp >> 2) * 64;

    #pragma unroll
    for (int br = 0; br < 2; br++) {
        const __half* Og = g_on + (size_t)br * N_TOK * DIMC;
        const __half* Wg = g_pwh + (size_t)br * DIMC * DIMC;
        unsigned od = sb + (unsigned)br * 17408u;
        unsigned wd = sb + 34816u + (unsigned)br * 34816u;
        #pragma unroll
        for (int t = 0; t < 4; t++) {
            int i = t * 256 + tid;
            int r = i >> 4, seg = i & 15;
            cp16(od + (unsigned)r * (PAD * 2) + (unsigned)seg * 16u,
                 (const char*)(Og + (size_t)(nb + r) * DIMC) + seg * 16);
        }
        #pragma unroll
        for (int t = 0; t < 8; t++) {
            int i = t * 256 + tid;
            int r = i >> 4, seg = i & 15;
            cp16(wd + (unsigned)r * (PAD * 2) + (unsigned)seg * 16u,
                 (const char*)(Wg + (size_t)r * DIMC) + seg * 16);
        }
    }
    CP_COMMIT();
    CP_WAIT(0);
    __syncthreads();

    float acc[8][4];
    #pragma unroll
    for (int n = 0; n < 8; n++)
        #pragma unroll
        for (int r = 0; r < 4; r++) acc[n][r] = 0.f;

    #pragma unroll
    for (int br = 0; br < 2; br++) {
        const __half* Oa  = smh + br * (64 * PAD);
        const __half* Wb2 = smh + 2 * (64 * PAD) + br * (128 * PAD);
        #pragma unroll
        for (int k = 0; k < 8; k++) {
            int k0 = k * 16;
            unsigned a0 = *(const unsigned*)(Oa + (q0 + rg)     * PAD + k0 + 2 * cg);
            unsigned a1 = *(const unsigned*)(Oa + (q0 + rg + 8) * PAD + k0 + 2 * cg);
            unsigned a2 = *(const unsigned*)(Oa + (q0 + rg)     * PAD + k0 + 8 + 2 * cg);
            unsigned a3 = *(const unsigned*)(Oa + (q0 + rg + 8) * PAD + k0 + 8 + 2 * cg);
            #pragma unroll
            for (int n = 0; n < 8; n++) {
                unsigned b0 = *(const unsigned*)(Wb2 + (e0 + n * 8 + rg) * PAD + k0 + 2 * cg);
                unsigned b1 = *(const unsigned*)(Wb2 + (e0 + n * 8 + rg) * PAD + k0 + 8 + 2 * cg);
                mma16(acc[n], a0, a1, a2, a3, b0, b1);
            }
        }
    }

    int tok0 = nb + q0 + rg, tok1 = tok0 + 8;
    #pragma unroll
    for (int n = 0; n < 8; n++) {
        int e = e0 + n * 8 + 2 * cg;
        float b0v = pbo[e] + pbb[e];
        float b1v = pbo[e + 1] + pbb[e + 1];
        *(unsigned*)(g_amh + (size_t)tok0 * DIMC + e) = packh2(acc[n][0] + b0v, acc[n][1] + b1v);
        *(unsigned*)(g_amh + (size_t)tok1 * DIMC + e) = packh2(acc[n][2] + b0v, acc[n][3] + b1v);
    }
}

// ---------------------------------------------------------------------------
// Kernel 4: 3x3 conv as 9 per-tap fp16 GEMMs (R8 version).  grid 96, 256 thr.
// ---------------------------------------------------------------------------
#define ICP    136
#define INROW  13328
#define INW    39984
#define INWB   79968u
#define WBUF   17408
#define WBUFB  34816u
#define SMEM_CONV 149600u

__global__ void __launch_bounds__(256, 1) conv_mma_kernel(const float* __restrict__ bias,
                                                          float* __restrict__ out)
{
    __half* smh = (__half*)dynsm;
    unsigned sb = smem_u32(dynsm);
    int tid  = threadIdx.x;
    int warp = tid >> 5, lane = tid & 31;
    int y    = blockIdx.x;
    int rg   = lane >> 2, cg = lane & 3;
    int oc0  = warp * 16;

    uint4 z4 = make_uint4(0, 0, 0, 0);
    #pragma unroll
    for (int yy = 0; yy < 3; yy++) {
        int yr = y + yy - 1;
        if (yr < 0 || yr >= 96) {
            for (int i = tid; i < INROW / 8; i += 256)
                *(uint4*)(smh + yy * INROW + i * 8) = z4;
        } else {
            if (tid < 17)       *(uint4*)(smh + (yy * 98 + 0)  * ICP + tid * 8)        = z4;
            else if (tid < 34)  *(uint4*)(smh + (yy * 98 + 97) * ICP + (tid - 17) * 8) = z4;
            for (int i = tid; i < 1536; i += 256) {
                int px = i >> 4, seg = i & 15;
                cp16(sb + (unsigned)((yy * 98 + px + 1) * ICP) * 2u + (unsigned)seg * 16u,
                     (const char*)(g_amh + ((size_t)yr * 96 + px) * DIMC) + seg * 16);
            }
        }
    }
    for (int i = tid; i < 2048; i += 256) {
        int oc = i >> 4, seg = i & 15;
        cp16(sb + INWB + (unsigned)(oc * ICP) * 2u + (unsigned)seg * 16u,
             (const char*)(g_wh + (size_t)oc * DIMC) + seg * 16);
    }
    CP_COMMIT();

    float acc[12][4];
    #pragma unroll
    for (int n = 0; n < 12; n++)
        #pragma unroll
        for (int r = 0; r < 4; r++) acc[n][r] = 0.f;

    for (int tap = 0; tap < 9; tap++) {
        if (tap > 0) __syncthreads();
        if (tap < 8) {
            const __half* src = g_wh + (size_t)(tap + 1) * DIMC * DIMC;
            unsigned dst = sb + INWB + (unsigned)((tap + 1) & 1) * WBUFB;
            for (int i = tid; i < 2048; i += 256) {
                int oc = i >> 4, seg = i & 15;
                cp16(dst + (unsigned)(oc * ICP) * 2u + (unsigned)seg * 16u,
                     (const char*)(src + (size_t)oc * DIMC) + seg * 16);
            }
            CP_COMMIT();
            CP_WAIT(1);
        } else {
            CP_WAIT(0);
        }
        __syncthreads();

        const __half* Wv = smh + INW + (tap & 1) * WBUF;
        int ky = tap / 3, kx = tap % 3;
        const __half* Iny = smh + ky * INROW;

        #pragma unroll
        for (int ks = 0; ks < 8; ks++) {
            int k0 = ks * 16;
            unsigned a0 = *(const unsigned*)(Wv + (oc0 + rg)     * ICP + k0 + 2 * cg);
            unsigned a1 = *(const unsigned*)(Wv + (oc0 + rg + 8) * ICP + k0 + 2 * cg);
            unsigned a2 = *(const unsigned*)(Wv + (oc0 + rg)     * ICP + k0 + 8 + 2 * cg);
            unsigned a3 = *(const unsigned*)(Wv + (oc0 + rg + 8) * ICP + k0 + 8 + 2 * cg);
            #pragma unroll
            for (int nb2 = 0; nb2 < 12; nb2++) {
                const __half* Bp = Iny + (nb2 * 8 + rg + kx) * ICP + k0;
                unsigned b0 = *(const unsigned*)(Bp + 2 * cg);
                unsigned b1 = *(const unsigned*)(Bp + 8 + 2 * cg);
                mma16(acc[nb2], a0, a1, a2, a3, b0, b1);
            }
        }
    }

    float bv0 = bias[oc0 + rg], bv1 = bias[oc0 + rg + 8];
    float* o0 = out + (size_t)(oc0 + rg)     * N_TOK + y * 96;
    float* o1 = out + (size_t)(oc0 + rg + 8) * N_TOK + y * 96;
    #pragma unroll
    for (int nb2 = 0; nb2 < 12; nb2++) {
        int col = nb2 * 8 + 2 * cg;
        *(float2*)(o0 + col) = make_float2(acc[nb2][0] + bv0, acc[nb2][1] + bv0);
        *(float2*)(o1 + col) = make_float2(acc[nb2][2] + bv1, acc[nb2][3] + bv1);
    }
}

// ---------------------------------------------------------------------------
extern "C" void kernel_launch(void* const* d_in, const int* in_sizes, int n_in,
                              void* d_out, int out_size)
{
    const float* x    = (const float*)d_in[0];
    const float* fm   = (const float*)d_in[1];
    const float* hm   = (const float*)d_in[2];
    const float* qwo  = (const float*)d_in[3];
    const float* kwo  = (const float*)d_in[4];
    const float* vwo  = (const float*)d_in[5];
    const float* pwo  = (const float*)d_in[6];
    const float* pbo  = (const float*)d_in[7];
    const float* qwb  = (const float*)d_in[8];
    const float* kwb  = (const float*)d_in[9];
    const float* vwb  = (const float*)d_in[10];
    const float* pwb  = (const float*)d_in[11];
    const float* pbb  = (const float*)d_in[12];
    const float* cw   = (const float*)d_in[13];
    const float* cb   = (const float*)d_in[14];
    float* out = (float*)d_out;

    prep_w_kernel<<<576, 256>>>(cw, qwo, kwo, vwo, qwb, kwb, vwb, pwo, pwb);

    cudaFuncSetAttribute(qkv_mma_kernel, cudaFuncAttributeMaxDynamicSharedMemorySize,
                         (int)(3 * TILEB));
    qkv_mma_kernel<<<dim3(72, 3), 256, 3 * TILEB>>>(x, fm, hm);

    cudaFuncSetAttribute(flash_mma_kernel, cudaFuncAttributeMaxDynamicSharedMemorySize,
                         (int)SMEM_FLASH);
    flash_mma_kernel<<<dim3(72, 2), 256, SMEM_FLASH>>>();

    cudaFuncSetAttribute(proj_mma_kernel, cudaFuncAttributeMaxDynamicSharedMemorySize,
                         (int)PROJ_SMEM);
    proj_mma_kernel<<<144, 256, PROJ_SMEM>>>(pbo, pbb);

    cudaFuncSetAttribute(conv_mma_kernel, cudaFuncAttributeMaxDynamicSharedMemorySize,
                         (int)SMEM_CONV);
    conv_mma_kernel<<<96, 256, SMEM_CONV>>>(cb, out);
}

// round 17
// speedup vs baseline: 1.0691x; 1.0691x over previous
#include <cuda_runtime.h>
#include <cuda_fp16.h>
#include <math.h>

#define N_TOK 9216
#define DIMC  128

// ---------------- scratch ----------------
__device__ __half g_q [2u * N_TOK * DIMC];     // [br][n][d] fp16, 0.25*log2e*mask folded
__device__ __half g_k [2u * N_TOK * DIMC];     // [br][n][d] fp16, mask folded
__device__ __half g_v [2u * N_TOK * DIMC];     // [br][d][n] fp16 (transposed), mask folded
__device__ __half g_on[2u * N_TOK * DIMC];     // [br][n][d] fp16 attention output
__device__ __half g_amh[(size_t)N_TOK * DIMC]; // [pixel][ch] fp16 (proj out)
__device__ __half g_wh [9u * DIMC * DIMC];     // [tap][oc][ic] fp16 conv weights
__device__ __half g_wqkv[6u * DIMC * DIMC];    // [b][d][c] fp16 qkv weights
__device__ __half g_pwh[2u * DIMC * DIMC];     // [br][e][d] fp16 proj weights

extern __shared__ char dynsm[];

// ---------------- helpers ----------------
__device__ __forceinline__ unsigned smem_u32(const void* p) {
    unsigned a;
    asm("{ .reg .u64 t; cvta.to.shared.u64 t, %1; cvt.u32.u64 %0, t; }" : "=r"(a) : "l"(p));
    return a;
}
__device__ __forceinline__ void cp16(unsigned dst, const void* src) {
    asm volatile("cp.async.cg.shared.global [%0], [%1], 16;" :: "r"(dst), "l"(src));
}
#define CP_COMMIT() asm volatile("cp.async.commit_group;" ::: "memory")
#define CP_WAIT(n)  asm volatile("cp.async.wait_group %0;" :: "n"(n) : "memory")

__device__ __forceinline__ void mma16(float* d, unsigned a0, unsigned a1, unsigned a2,
                                      unsigned a3, unsigned b0, unsigned b1) {
    asm volatile("mma.sync.aligned.m16n8k16.row.col.f32.f16.f16.f32 "
        "{%0,%1,%2,%3}, {%4,%5,%6,%7}, {%8,%9}, {%0,%1,%2,%3};"
        : "+f"(d[0]), "+f"(d[1]), "+f"(d[2]), "+f"(d[3])
        : "r"(a0), "r"(a1), "r"(a2), "r"(a3), "r"(b0), "r"(b1));
}
__device__ __forceinline__ void ldsm4(unsigned& r0, unsigned& r1, unsigned& r2,
                                      unsigned& r3, unsigned addr) {
    asm volatile("ldmatrix.sync.aligned.m8n8.x4.shared.b16 {%0,%1,%2,%3}, [%4];"
        : "=r"(r0), "=r"(r1), "=r"(r2), "=r"(r3) : "r"(addr));
}
__device__ __forceinline__ unsigned packh2(float lo, float hi) {
    __half2 h = __floats2half2_rn(lo, hi);
    return *(unsigned*)&h;
}
__device__ __forceinline__ float ex2(float x) {
    float r;
    asm("ex2.approx.f32 %0, %1;" : "=f"(r) : "f"(x));
    return r;
}

// ---------------------------------------------------------------------------
// Kernel 0: fp16 weight prep.
// ---------------------------------------------------------------------------
__global__ void prep_w_kernel(const float* __restrict__ cw,
                              const float* __restrict__ qwo, const float* __restrict__ kwo,
                              const float* __restrict__ vwo,
                              const float* __restrict__ qwb, const float* __restrict__ kwb,
                              const float* __restrict__ vwb,
                              const float* __restrict__ pwo, const float* __restrict__ pwb)
{
    int i = blockIdx.x * 256 + threadIdx.x;
    if (i < 9 * 128 * 128) {
        int tap = i >> 14;
        int rem = i & 16383;
        int oc  = rem >> 7;
        int ic  = rem & 127;
        g_wh[i] = __float2half(cw[((size_t)oc * 128 + ic) * 9 + tap]);
    }
    if (i < 6 * 16384) {
        int b = i >> 14, e = i & 16383;
        const float* W = (b == 0) ? qwo : (b == 1) ? kwo : (b == 2) ? vwo
                       : (b == 3) ? qwb : (b == 4) ? kwb : vwb;
        g_wqkv[i] = __float2half(W[e]);
    }
    if (i < 2 * 16384) {
        int b = i >> 14, e = i & 16383;
        g_pwh[i] = __float2half(b ? pwb[e] : pwo[e]);
    }
}

// ---------------------------------------------------------------------------
// Kernel 1: qkv via mma.  grid (72, 3) — kind-major, both branches per CTA.
// ---------------------------------------------------------------------------
#define PAD  136
#define PADW 68
#define TILEB 34816u     // 128*136*2 bytes

__global__ void __launch_bounds__(256) qkv_mma_kernel(const float* __restrict__ x,
                                                      const float* __restrict__ fm,
                                                      const float* __restrict__ hm)
{
    __half* smh = (__half*)dynsm;           // A [128][136] | W0 | W1
    unsigned sb = smem_u32(dynsm);

    int kind = blockIdx.y;
    int nb   = blockIdx.x * 128;
    int tid = threadIdx.x;
    int warp = tid >> 5, lane = tid & 31;
    int rg = lane >> 2, cg = lane & 3;
    int q0 = warp * 16;
    const float* X = (kind == 1) ? fm : x;

    #pragma unroll
    for (int br = 0; br < 2; br++) {
        const __half* Wg = g_wqkv + (size_t)(br * 3 + kind) * DIMC * DIMC;
        unsigned wd = sb + (unsigned)(1 + br) * TILEB;
        #pragma unroll
        for (int t = 0; t < 8; t++) {
            int i = t * 256 + tid;
            int d = i >> 4, seg = i & 15;
            cp16(wd + (unsigned)d * (PAD * 2) + (unsigned)seg * 16u,
                 (const char*)(Wg + (size_t)d * DIMC) + seg * 16);
        }
    }
    CP_COMMIT();

    unsigned* At2 = (unsigned*)smh;
    #pragma unroll
    for (int t = 0; t < 32; t++) {
        int idx = t * 256 + tid;
        int n = idx & 127, cp = idx >> 7;
        float v0 = X[(size_t)(2 * cp)     * N_TOK + nb + n];
        float v1 = X[(size_t)(2 * cp + 1) * N_TOK + nb + n];
        At2[n * PADW + cp] = packh2(v0, v1);
    }
    CP_WAIT(0);
    __syncthreads();

    unsigned af[8][4];
    #pragma unroll
    for (int k = 0; k < 8; k++) {
        int k0 = k * 16;
        af[k][0] = *(const unsigned*)(smh + (q0 + rg)     * PAD + k0 + 2 * cg);
        af[k][1] = *(const unsigned*)(smh + (q0 + rg + 8) * PAD + k0 + 2 * cg);
        af[k][2] = *(const unsigned*)(smh + (q0 + rg)     * PAD + k0 + 8 + 2 * cg);
        af[k][3] = *(const unsigned*)(smh + (q0 + rg + 8) * PAD + k0 + 8 + 2 * cg);
    }

    float qs = (kind == 0) ? 0.25f * 1.44269504f : 1.0f;
    int tok0 = nb + q0 + rg, tok1 = tok0 + 8;
    float h0 = hm[tok0], h1 = hm[tok1];

    #pragma unroll
    for (int br = 0; br < 2; br++) {
        const __half* Wsm = smh + (1 + br) * (128 * PAD);
        float acc[16][4];
        #pragma unroll
        for (int n = 0; n < 16; n++)
            #pragma unroll
            for (int r = 0; r < 4; r++) acc[n][r] = 0.f;

        #pragma unroll
        for (int k = 0; k < 8; k++) {
            int k0 = k * 16;
            #pragma unroll
            for (int n = 0; n < 16; n++) {
                unsigned b0 = *(const unsigned*)(Wsm + (n * 8 + rg) * PAD + k0 + 2 * cg);
                unsigned b1 = *(const unsigned*)(Wsm + (n * 8 + rg) * PAD + k0 + 8 + 2 * cg);
                mma16(acc[n], af[k][0], af[k][1], af[k][2], af[k][3], b0, b1);
            }
        }

        float f0 = ((br == 0) ? (h0 > 0.3f ? 1.f : 0.01f) : (h0 > 0.3f ? 0.01f : 1.f)) * qs;
        float f1 = ((br == 0) ? (h1 > 0.3f ? 1.f : 0.01f) : (h1 > 0.3f ? 0.01f : 1.f)) * qs;

        if (kind != 2) {
            __half* out = ((kind == 0) ? g_q : g_k) + (size_t)br * N_TOK * DIMC;
            #pragma unroll
            for (int n = 0; n < 16; n++) {
                int col = n * 8 + 2 * cg;
                *(unsigned*)(out + (size_t)tok0 * DIMC + col) = packh2(acc[n][0] * f0, acc[n][1] * f0);
                *(unsigned*)(out + (size_t)tok1 * DIMC + col) = packh2(acc[n][2] * f1, acc[n][3] * f1);
            }
        } else {
            __half* tb = smh + 1 * (128 * PAD);
            __syncthreads();
            #pragma unroll
            for (int n = 0; n < 16; n++) {
                int col = n * 8 + 2 * cg;
                tb[(col)     * PAD + q0 + rg]     = __float2half(acc[n][0] * f0);
                tb[(col + 1) * PAD + q0 + rg]     = __float2half(acc[n][1] * f0);
                tb[(col)     * PAD + q0 + rg + 8] = __float2half(acc[n][2] * f1);
                tb[(col + 1) * PAD + q0 + rg + 8] = __float2half(acc[n][3] * f1);
            }
            __syncthreads();
            __half* outv = g_v + (size_t)br * N_TOK * DIMC;
            #pragma unroll
            for (int t = 0; t < 8; t++) {
                int i = t * 256 + tid;
                int d = i >> 4, seg = i & 15;
                uint4 v = *(const uint4*)(tb + d * PAD + seg * 8);
                *(uint4*)((char*)(outv + (size_t)d * N_TOK + nb) + seg * 16) = v;
            }
        }
    }
}

// ---------------------------------------------------------------------------
// Kernel 2: fp16 flash attention (R8: ldmatrix + hoisted Q frags + exp2,
// triple-buffered K/V, one barrier per tile).  grid (72, 2), 256 threads.
// ---------------------------------------------------------------------------
#define QSTRH  136
#define QROWB  272u
#define KV_OFF 34816u
#define KBYTES 17408u
#define BUF_SZ 35840u
#define SMEM_FLASH 142336u      // Q + 3 KV buffers

__device__ __forceinline__ void load_kv_async(const __half* __restrict__ Kg,
                                              const __half* __restrict__ Vg,
                                              unsigned sb, int kb, unsigned bufoff, int tid)
{
    #pragma unroll
    for (int t = 0; t < 4; t++) {
        int c = t * 256 + tid;
        int row = c >> 4, i = c & 15;
        cp16(sb + bufoff + (unsigned)row * QROWB + (unsigned)i * 16u,
             (const char*)(Kg + (size_t)(kb + row) * DIMC) + i * 16);
    }
    #pragma unroll
    for (int t = 0; t < 4; t++) {
        int c = t * 256 + tid;
        int row = c >> 3, i = c & 7;
        cp16(sb + bufoff + KBYTES + (unsigned)row * 144u + (unsigned)i * 16u,
             (const char*)(Vg + (size_t)row * N_TOK + kb) + i * 16);
    }
}

__global__ void __launch_bounds__(256, 1) flash_mma_kernel()
{
    const __half* smh = (const __half*)dynsm;
    unsigned sb = smem_u32(dynsm);
    int tid  = threadIdx.x;
    int warp = tid >> 5, lane = tid & 31;
    int branch = blockIdx.y;
    int qb     = blockIdx.x * 128;

    const __half* Qg = g_q + (size_t)branch * N_TOK * DIMC;
    const __half* Kg = g_k + (size_t)branch * N_TOK * DIMC;
    const __half* Vg = g_v + (size_t)branch * N_TOK * DIMC;

    #pragma unroll
    for (int t = 0; t < 8; t++) {
        int c = t * 256 + tid;
        int row = c >> 4, i = c & 15;
        cp16(sb + (unsigned)row * QROWB + (unsigned)i * 16u,
             (const char*)(Qg + (size_t)(qb + row) * DIMC) + i * 16);
    }
    CP_COMMIT();
    load_kv_async(Kg, Vg, sb, 0, KV_OFF, tid);
    CP_COMMIT();

    int q0 = warp * 16;
    int rg = lane >> 2;
    int cg = lane & 3;

    CP_WAIT(1);            // Q resident
    __syncthreads();

    unsigned qf[8][4];
    #pragma unroll
    for (int k = 0; k < 8; k++) {
        int k0 = k * 16;
        qf[k][0] = *(const unsigned*)(smh + (q0 + rg)     * QSTRH + k0 + 2 * cg);
        qf[k][1] = *(const unsigned*)(smh + (q0 + rg + 8) * QSTRH + k0 + 2 * cg);
        qf[k][2] = *(const unsigned*)(smh + (q0 + rg)     * QSTRH + k0 + 8 + 2 * cg);
        qf[k][3] = *(const unsigned*)(smh + (q0 + rg + 8) * QSTRH + k0 + 8 + 2 * cg);
    }

    unsigned rowsel = (unsigned)(((lane >> 4) * 8 + (lane & 7)));
    unsigned kh16   = (unsigned)(((lane >> 3) & 1) * 16);

    float o[16][4];
    #pragma unroll
    for (int n = 0; n < 16; n++)
        #pragma unroll
        for (int r = 0; r < 4; r++) o[n][r] = 0.f;
    float l0 = 0.f, l1 = 0.f;

    for (int j = 0; j < 144; j++) {
        if (j + 1 < 144) {
            load_kv_async(Kg, Vg, sb, (j + 1) * 64,
                          KV_OFF + (unsigned)((j + 1) % 3) * BUF_SZ, tid);
            CP_COMMIT();
            CP_WAIT(1);
        } else {
            CP_WAIT(0);
        }
        __syncthreads();    // single barrier per tile (3rd buffer removes WAR hazard)

        unsigned KrowB = sb + KV_OFF + (unsigned)(j % 3) * BUF_SZ + rowsel * 272u + kh16;
        unsigned VrowB = sb + KV_OFF + (unsigned)(j % 3) * BUF_SZ + KBYTES + rowsel * 144u + kh16;

        // ---- S = Q . K^T ----
        float s[8][4];
        #pragma unroll
        for (int n = 0; n < 8; n++)
            #pragma unroll
            for (int r = 0; r < 4; r++) s[n][r] = 0.f;

        #pragma unroll
        for (int k = 0; k < 8; k++) {
            #pragma unroll
            for (int g = 0; g < 4; g++) {
                unsigned b0a, b1a, b0b, b1b;
                ldsm4(b0a, b1a, b0b, b1b, KrowB + (unsigned)g * 4352u + (unsigned)k * 32u);
                mma16(s[2 * g],     qf[k][0], qf[k][1], qf[k][2], qf[k][3], b0a, b1a);
                mma16(s[2 * g + 1], qf[k][0], qf[k][1], qf[k][2], qf[k][3], b0b, b1b);
            }
        }

        // ---- P = exp2(S) (log2e pre-folded); rowsum; pack ----
        unsigned ph0[8], ph1[8];
        #pragma unroll
        for (int n = 0; n < 8; n++) {
            float p0 = ex2(s[n][0]);
            float p1 = ex2(s[n][1]);
            float p2 = ex2(s[n][2]);
            float p3 = ex2(s[n][3]);
            l0 += p0 + p1;
            l1 += p2 + p3;
            ph0[n] = packh2(p0, p1);
            ph1[n] = packh2(p2, p3);
        }

        // ---- O += P . V ----
        #pragma unroll
        for (int kb2 = 0; kb2 < 4; kb2++) {
            unsigned a0 = ph0[2 * kb2];
            unsigned a1 = ph1[2 * kb2];
            unsigned a2 = ph0[2 * kb2 + 1];
            unsigned a3 = ph1[2 * kb2 + 1];
            #pragma unroll
            for (int g = 0; g < 8; g++) {
                unsigned b0a, b1a, b0b, b1b;
                ldsm4(b0a, b1a, b0b, b1b, VrowB + (unsigned)g * 2304u + (unsigned)kb2 * 32u);
                mma16(o[2 * g],     a0, a1, a2, a3, b0a, b1a);
                mma16(o[2 * g + 1], a0, a1, a2, a3, b0b, b1b);
            }
        }
    }

    l0 += __shfl_xor_sync(0xffffffffu, l0, 1);
    l0 += __shfl_xor_sync(0xffffffffu, l0, 2);
    l1 += __shfl_xor_sync(0xffffffffu, l1, 1);
    l1 += __shfl_xor_sync(0xffffffffu, l1, 2);
    float inv0 = 1.f / l0, inv1 = 1.f / l1;

    __half* On = g_on + (size_t)branch * N_TOK * DIMC;
    int row_lo = qb + q0 + rg;
    int row_hi = row_lo + 8;
    #pragma unroll
    for (int n = 0; n < 16; n++) {
        int col = n * 8 + 2 * cg;
        *(unsigned*)(On + (size_t)row_lo * DIMC + col) = packh2(o[n][0] * inv0, o[n][1] * inv0);
        *(unsigned*)(On + (size_t)row_hi * DIMC + col) = packh2(o[n][2] * inv1, o[n][3] * inv1);
    }
}

// ---------------------------------------------------------------------------
// Kernel 3: projection via mma.  grid 144 (64-token tiles), 256 threads.
// ---------------------------------------------------------------------------
#define PROJ_SMEM 104448u

__global__ void __launch_bounds__(256) proj_mma_kernel(const float* __restrict__ pbo,
                                                       const float* __restrict__ pbb)
{
    __half* smh = (__half*)dynsm;
    unsigned sb = smem_u32(dynsm);
    int nb  = blockIdx.x * 64;
    int tid = threadIdx.x;
    int warp = tid >> 5, lane = tid & 31;
    int rg = lane >> 2, cg = lane & 3;
    int q0 = (warp & 3) * 16;
    int e0 = (warp >> 2) * 64;

    #pragma unroll
    for (int br = 0; br < 2; br++) {
        const __half* Og = g_on + (size_t)br * N_TOK * DIMC;
        const __half* Wg = g_pwh + (size_t)br * DIMC * DIMC;
        unsigned od = sb + (unsigned)br * 17408u;
        unsigned wd = sb + 34816u + (unsigned)br * 34816u;
        #pragma unroll
        for (int t = 0; t < 4; t++) {
            int i = t * 256 + tid;
            int r = i >> 4, seg = i & 15;
            cp16(od + (unsigned)r * (PAD * 2) + (unsigned)seg * 16u,
                 (const char*)(Og + (size_t)(nb + r) * DIMC) + seg * 16);
        }
        #pragma unroll
        for (int t = 0; t < 8; t++) {
            int i = t * 256 + tid;
            int r = i >> 4, seg = i & 15;
            cp16(wd + (unsigned)r * (PAD * 2) + (unsigned)seg * 16u,
                 (const char*)(Wg + (size_t)r * DIMC) + seg * 16);
        }
    }
    CP_COMMIT();
    CP_WAIT(0);
    __syncthreads();

    float acc[8][4];
    #pragma unroll
    for (int n = 0; n < 8; n++)
        #pragma unroll
        for (int r = 0; r < 4; r++) acc[n][r] = 0.f;

    #pragma unroll
    for (int br = 0; br < 2; br++) {
        const __half* Oa  = smh + br * (64 * PAD);
        const __half* Wb2 = smh + 2 * (64 * PAD) + br * (128 * PAD);
        #pragma unroll
        for (int k = 0; k < 8; k++) {
            int k0 = k * 16;
            unsigned a0 = *(const unsigned*)(Oa + (q0 + rg)     * PAD + k0 + 2 * cg);
            unsigned a1 = *(const unsigned*)(Oa + (q0 + rg + 8) * PAD + k0 + 2 * cg);
            unsigned a2 = *(const unsigned*)(Oa + (q0 + rg)     * PAD + k0 + 8 + 2 * cg);
            unsigned a3 = *(const unsigned*)(Oa + (q0 + rg + 8) * PAD + k0 + 8 + 2 * cg);
            #pragma unroll
            for (int n = 0; n < 8; n++) {
                unsigned b0 = *(const unsigned*)(Wb2 + (e0 + n * 8 + rg) * PAD + k0 + 2 * cg);
                unsigned b1 = *(const unsigned*)(Wb2 + (e0 + n * 8 + rg) * PAD + k0 + 8 + 2 * cg);
                mma16(acc[n], a0, a1, a2, a3, b0, b1);
            }
        }
    }

    int tok0 = nb + q0 + rg, tok1 = tok0 + 8;
    #pragma unroll
    for (int n = 0; n < 8; n++) {
        int e = e0 + n * 8 + 2 * cg;
        float b0v = pbo[e] + pbb[e];
        float b1v = pbo[e + 1] + pbb[e + 1];
        *(unsigned*)(g_amh + (size_t)tok0 * DIMC + e) = packh2(acc[n][0] + b0v, acc[n][1] + b1v);
        *(unsigned*)(g_amh + (size_t)tok1 * DIMC + e) = packh2(acc[n][2] + b0v, acc[n][3] + b1v);
    }
}

// ---------------------------------------------------------------------------
// Kernel 4: 3x3 conv as 9 per-tap fp16 GEMMs (R8 version).  grid 96, 256 thr.
// ---------------------------------------------------------------------------
#define ICP    136
#define INROW  13328
#define INW    39984
#define INWB   79968u
#define WBUF   17408
#define WBUFB  34816u
#define SMEM_CONV 149600u

__global__ void __launch_bounds__(256, 1) conv_mma_kernel(const float* __restrict__ bias,
                                                          float* __restrict__ out)
{
    __half* smh = (__half*)dynsm;
    unsigned sb = smem_u32(dynsm);
    int tid  = threadIdx.x;
    int warp = tid >> 5, lane = tid & 31;
    int y    = blockIdx.x;
    int rg   = lane >> 2, cg = lane & 3;
    int oc0  = warp * 16;

    uint4 z4 = make_uint4(0, 0, 0, 0);
    #pragma unroll
    for (int yy = 0; yy < 3; yy++) {
        int yr = y + yy - 1;
        if (yr < 0 || yr >= 96) {
            for (int i = tid; i < INROW / 8; i += 256)
                *(uint4*)(smh + yy * INROW + i * 8) = z4;
        } else {
            if (tid < 17)       *(uint4*)(smh + (yy * 98 + 0)  * ICP + tid * 8)        = z4;
            else if (tid < 34)  *(uint4*)(smh + (yy * 98 + 97) * ICP + (tid - 17) * 8) = z4;
            for (int i = tid; i < 1536; i += 256) {
                int px = i >> 4, seg = i & 15;
                cp16(sb + (unsigned)((yy * 98 + px + 1) * ICP) * 2u + (unsigned)seg * 16u,
                     (const char*)(g_amh + ((size_t)yr * 96 + px) * DIMC) + seg * 16);
            }
        }
    }
    for (int i = tid; i < 2048; i += 256) {
        int oc = i >> 4, seg = i & 15;
        cp16(sb + INWB + (unsigned)(oc * ICP) * 2u + (unsigned)seg * 16u,
             (const char*)(g_wh + (size_t)oc * DIMC) + seg * 16);
    }
    CP_COMMIT();

    float acc[12][4];
    #pragma unroll
    for (int n = 0; n < 12; n++)
        #pragma unroll
        for (int r = 0; r < 4; r++) acc[n][r] = 0.f;

    for (int tap = 0; tap < 9; tap++) {
        if (tap > 0) __syncthreads();
        if (tap < 8) {
            const __half* src = g_wh + (size_t)(tap + 1) * DIMC * DIMC;
            unsigned dst = sb + INWB + (unsigned)((tap + 1) & 1) * WBUFB;
            for (int i = tid; i < 2048; i += 256) {
                int oc = i >> 4, seg = i & 15;
                cp16(dst + (unsigned)(oc * ICP) * 2u + (unsigned)seg * 16u,
                     (const char*)(src + (size_t)oc * DIMC) + seg * 16);
            }
            CP_COMMIT();
            CP_WAIT(1);
        } else {
            CP_WAIT(0);
        }
        __syncthreads();

        const __half* Wv = smh + INW + (tap & 1) * WBUF;
        int ky = tap / 3, kx = tap % 3;
        const __half* Iny = smh + ky * INROW;

        #pragma unroll
        for (int ks = 0; ks < 8; ks++) {
            int k0 = ks * 16;
            unsigned a0 = *(const unsigned*)(Wv + (oc0 + rg)     * ICP + k0 + 2 * cg);
            unsigned a1 = *(const unsigned*)(Wv + (oc0 + rg + 8) * ICP + k0 + 2 * cg);
            unsigned a2 = *(const unsigned*)(Wv + (oc0 + rg)     * ICP + k0 + 8 + 2 * cg);
            unsigned a3 = *(const unsigned*)(Wv + (oc0 + rg + 8) * ICP + k0 + 8 + 2 * cg);
            #pragma unroll
            for (int nb2 = 0; nb2 < 12; nb2++) {
                const __half* Bp = Iny + (nb2 * 8 + rg + kx) * ICP + k0;
                unsigned b0 = *(const unsigned*)(Bp + 2 * cg);
                unsigned b1 = *(const unsigned*)(Bp + 8 + 2 * cg);
                mma16(acc[nb2], a0, a1, a2, a3, b0, b1);
            }
        }
    }

    float bv0 = bias[oc0 + rg], bv1 = bias[oc0 + rg + 8];
    float* o0 = out + (size_t)(oc0 + rg)     * N_TOK + y * 96;
    float* o1 = out + (size_t)(oc0 + rg + 8) * N_TOK + y * 96;
    #pragma unroll
    for (int nb2 = 0; nb2 < 12; nb2++) {
        int col = nb2 * 8 + 2 * cg;
        *(float2*)(o0 + col) = make_float2(acc[nb2][0] + bv0, acc[nb2][1] + bv0);
        *(float2*)(o1 + col) = make_float2(acc[nb2][2] + bv1, acc[nb2][3] + bv1);
    }
}

// ---------------------------------------------------------------------------
extern "C" void kernel_launch(void* const* d_in, const int* in_sizes, int n_in,
                              void* d_out, int out_size)
{
    const float* x    = (const float*)d_in[0];
    const float* fm   = (const float*)d_in[1];
    const float* hm   = (const float*)d_in[2];
    const float* qwo  = (const float*)d_in[3];
    const float* kwo  = (const float*)d_in[4];
    const float* vwo  = (const float*)d_in[5];
    const float* pwo  = (const float*)d_in[6];
    const float* pbo  = (const float*)d_in[7];
    const float* qwb  = (const float*)d_in[8];
    const float* kwb  = (const float*)d_in[9];
    const float* vwb  = (const float*)d_in[10];
    const float* pwb  = (const float*)d_in[11];
    const float* pbb  = (const float*)d_in[12];
    const float* cw   = (const float*)d_in[13];
    const float* cb   = (const float*)d_in[14];
    float* out = (float*)d_out;

    prep_w_kernel<<<576, 256>>>(cw, qwo, kwo, vwo, qwb, kwb, vwb, pwo, pwb);

    cudaFuncSetAttribute(qkv_mma_kernel, cudaFuncAttributeMaxDynamicSharedMemorySize,
                         (int)(3 * TILEB));
    qkv_mma_kernel<<<dim3(72, 3), 256, 3 * TILEB>>>(x, fm, hm);

    cudaFuncSetAttribute(flash_mma_kernel, cudaFuncAttributeMaxDynamicSharedMemorySize,
                         (int)SMEM_FLASH);
    flash_mma_kernel<<<dim3(72, 2), 256, SMEM_FLASH>>>();

    cudaFuncSetAttribute(proj_mma_kernel, cudaFuncAttributeMaxDynamicSharedMemorySize,
                         (int)PROJ_SMEM);
    proj_mma_kernel<<<144, 256, PROJ_SMEM>>>(pbo, pbb);

    cudaFuncSetAttribute(conv_mma_kernel, cudaFuncAttributeMaxDynamicSharedMemorySize,
                         (int)SMEM_CONV);
    conv_mma_kernel<<<96, 256, SMEM_CONV>>>(cb, out);
}